// round 14
// baseline (speedup 1.0000x reference)
#include <cuda_runtime.h>
#include <cstdint>

#define B_DIM 4096
#define K_DIM 64
#define D_DIM 512
#define POOL_N 1000000
#define THREADS 512
#define NWARP (THREADS / 32)           // 16 warps
#define ROWS_PER_WARP (K_DIM / NWARP)  // 4 rows per warp, in 2 batches of 2
#define NBATCH 2
#define RPB 2                          // rows per batch

// smem: partials[NWARP][D] | x[D]  = 32KB + 2KB
#define SMEM_FLOATS (NWARP * D_DIM + D_DIM)
#define SMEM_BYTES (SMEM_FLOATS * sizeof(float))

__global__ void __launch_bounds__(THREADS, 2)
sparse_exec_kernel(const float* __restrict__ x,
                   const int* __restrict__ indices,
                   const float* __restrict__ weights,
                   const float* __restrict__ pool,
                   float* __restrict__ out) {
    extern __shared__ float smem[];
    float* s_part = smem;                      // NWARP * D
    float* s_x    = smem + NWARP * D_DIM;      // D

    const int b    = blockIdx.x;
    const int tid  = threadIdx.x;
    const int warp = tid >> 5;
    const int lane = tid & 31;

    // ---- indices + weights for this warp's 4 rows (issue first: idx->pool chain) ----
    int   idx[ROWS_PER_WARP];
    float w[ROWS_PER_WARP];
#pragma unroll
    for (int r = 0; r < ROWS_PER_WARP; r++) {
        int k = warp * ROWS_PER_WARP + r;
        idx[r] = indices[(size_t)b * K_DIM + k];
        w[r]   = __ldg(&weights[(size_t)b * K_DIM + k]);
    }
#pragma unroll
    for (int r = 0; r < ROWS_PER_WARP; r++) {
        int t = idx[r];
        idx[r] = t < 0 ? 0 : (t >= POOL_N ? POOL_N - 1 : t);
    }

    // x load -> smem (overlaps batch-0 pool load latency below)
    float xv = x[(size_t)b * D_DIM + tid];

    // ---- batch 0 pool loads issued before the barrier (no smem dependence) ----
    float4 v[RPB][4];
#pragma unroll
    for (int r = 0; r < RPB; r++) {
        const float4* prow = (const float4*)(pool + (size_t)idx[r] * D_DIM);
#pragma unroll
        for (int i = 0; i < 4; i++)
            v[r][i] = __ldg(&prow[i * 32 + lane]);
    }

    s_x[tid] = xv;
    __syncthreads();

    const float4* sx4 = (const float4*)s_x;
    float p[4][4];   // persistent weighted partial, 16 regs (p[i] = float4 as 4 floats)
#pragma unroll
    for (int i = 0; i < 4; i++)
#pragma unroll
        for (int c = 0; c < 4; c++) p[i][c] = 0.0f;

#pragma unroll
    for (int bt = 0; bt < NBATCH; bt++) {
        if (bt > 0) {
            // load next batch into the same v registers
#pragma unroll
            for (int r = 0; r < RPB; r++) {
                const float4* prow =
                    (const float4*)(pool + (size_t)idx[bt * RPB + r] * D_DIM);
#pragma unroll
                for (int i = 0; i < 4; i++)
                    v[r][i] = __ldg(&prow[i * 32 + lane]);
            }
        }

        // dots vs x (x re-read from smem, conflict-free LDS.128)
        float dot[RPB];
#pragma unroll
        for (int r = 0; r < RPB; r++) {
            float d = 0.0f;
#pragma unroll
            for (int i = 0; i < 4; i++) {
                float4 xr = sx4[i * 32 + lane];
                d += v[r][i].x * xr.x + v[r][i].y * xr.y
                   + v[r][i].z * xr.z + v[r][i].w * xr.w;
            }
#pragma unroll
            for (int off = 16; off; off >>= 1)
                d += __shfl_xor_sync(0xffffffffu, d, off);
            dot[r] = d;
        }

        float wa[RPB];
#pragma unroll
        for (int r = 0; r < RPB; r++)
            wa[r] = tanhf(dot[r]) * w[bt * RPB + r];

        // accumulate weighted rows into persistent partial
#pragma unroll
        for (int i = 0; i < 4; i++) {
            p[i][0] += wa[0] * v[0][i].x + wa[1] * v[1][i].x;
            p[i][1] += wa[0] * v[0][i].y + wa[1] * v[1][i].y;
            p[i][2] += wa[0] * v[0][i].z + wa[1] * v[1][i].z;
            p[i][3] += wa[0] * v[0][i].w + wa[1] * v[1][i].w;
        }
    }

    // ---- store per-warp partial, reduce 16 partials, write out ----
    float4* pw = (float4*)(s_part + warp * D_DIM);
#pragma unroll
    for (int i = 0; i < 4; i++) {
        float4 q;
        q.x = p[i][0]; q.y = p[i][1]; q.z = p[i][2]; q.w = p[i][3];
        pw[i * 32 + lane] = q;
    }
    __syncthreads();

    float acc = xv;
#pragma unroll
    for (int wq = 0; wq < NWARP; wq++)
        acc += s_part[wq * D_DIM + tid];

    out[(size_t)b * D_DIM + tid] = acc;
}

extern "C" void kernel_launch(void* const* d_in, const int* in_sizes, int n_in,
                              void* d_out, int out_size) {
    const float* x       = (const float*)d_in[0];
    const int*   indices = (const int*)d_in[1];
    const float* weights = (const float*)d_in[2];
    const float* pool    = (const float*)d_in[3];
    float*       out     = (float*)d_out;

    cudaFuncSetAttribute(sparse_exec_kernel,
                         cudaFuncAttributeMaxDynamicSharedMemorySize, SMEM_BYTES);

    sparse_exec_kernel<<<B_DIM, THREADS, SMEM_BYTES>>>(x, indices, weights, pool, out);
}

// round 15
// speedup vs baseline: 1.2185x; 1.2185x over previous
#include <cuda_runtime.h>
#include <cstdint>

#define B_DIM 4096
#define K_DIM 64
#define D_DIM 512
#define POOL_N 1000000
#define THREADS 512
#define SPLIT 2
#define K_PER (K_DIM / SPLIT)          // 32 rows per CTA
#define NWARP (THREADS / 32)           // 16 warps
#define ROWS_PER_WARP (K_PER / NWARP)  // 2 rows per warp

// smem: partials[NWARP][D] | x[D]
#define SMEM_FLOATS (NWARP * D_DIM + D_DIM)
#define SMEM_BYTES (SMEM_FLOATS * sizeof(float))

// init: out = x (out is poisoned; gives REDs a base containing the residual)
#define INIT_THREADS 256
__global__ void __launch_bounds__(INIT_THREADS)
init_kernel(const float* __restrict__ x, float* __restrict__ out) {
    size_t i = (size_t)blockIdx.x * INIT_THREADS + threadIdx.x;
    ((float4*)out)[i] = ((const float4*)x)[i];
}

__global__ void __launch_bounds__(THREADS, 2)
sparse_gather_kernel(const float* __restrict__ x,
                     const int* __restrict__ indices,
                     const float* __restrict__ weights,
                     const float* __restrict__ pool,
                     float* __restrict__ out) {
    extern __shared__ float smem[];
    float* s_part = smem;                      // NWARP * D
    float* s_x    = smem + NWARP * D_DIM;      // D

    const int b     = blockIdx.x >> 1;
    const int split = blockIdx.x & 1;
    const int tid   = threadIdx.x;
    const int warp  = tid >> 5;
    const int lane  = tid & 31;
    const int kbase = split * K_PER;

    // ---- 1. indices + weights first (critical chain: idx -> pool) ----
    int idxs[ROWS_PER_WARP];
    float w[ROWS_PER_WARP];
#pragma unroll
    for (int r = 0; r < ROWS_PER_WARP; r++) {
        int k = warp * ROWS_PER_WARP + r;
        idxs[r] = indices[(size_t)b * K_DIM + kbase + k];
        w[r]    = __ldg(&weights[(size_t)b * K_DIM + kbase + k]);
    }

    // ---- 2. x load (overlaps index latency) ----
    float xv = x[(size_t)b * D_DIM + tid];

    // ---- 3. clamp + fire all 8 pool LDG.128 (MLP=8/thread) ----
#pragma unroll
    for (int r = 0; r < ROWS_PER_WARP; r++) {
        int t = idxs[r];
        idxs[r] = t < 0 ? 0 : (t >= POOL_N ? POOL_N - 1 : t);
    }
    float4 v[ROWS_PER_WARP][4];
#pragma unroll
    for (int r = 0; r < ROWS_PER_WARP; r++) {
        const float4* prow = (const float4*)(pool + (size_t)idxs[r] * D_DIM);
#pragma unroll
        for (int i = 0; i < 4; i++)
            v[r][i] = __ldg(&prow[i * 32 + lane]);
    }

    // ---- 4. x -> smem + barrier (hidden behind pool-load latency) ----
    s_x[tid] = xv;
    __syncthreads();

    const float4* sx4 = (const float4*)s_x;
    float4 xr[4];
#pragma unroll
    for (int i = 0; i < 4; i++)
        xr[i] = sx4[i * 32 + lane];

    // ---- 5. dots + warp reduce ----
    float dot[ROWS_PER_WARP];
#pragma unroll
    for (int r = 0; r < ROWS_PER_WARP; r++) {
        float d = 0.0f;
#pragma unroll
        for (int i = 0; i < 4; i++)
            d += v[r][i].x * xr[i].x + v[r][i].y * xr[i].y
               + v[r][i].z * xr[i].z + v[r][i].w * xr[i].w;
#pragma unroll
        for (int off = 16; off; off >>= 1)
            d += __shfl_xor_sync(0xffffffffu, d, off);
        dot[r] = d;
    }

    float wa[ROWS_PER_WARP];
#pragma unroll
    for (int r = 0; r < ROWS_PER_WARP; r++)
        wa[r] = tanhf(dot[r]) * w[r];

    // ---- 6. per-warp weighted partial from registers ----
    float4* pw = (float4*)(s_part + warp * D_DIM);
#pragma unroll
    for (int i = 0; i < 4; i++) {
        float4 p;
        p.x = wa[0] * v[0][i].x + wa[1] * v[1][i].x;
        p.y = wa[0] * v[0][i].y + wa[1] * v[1][i].y;
        p.z = wa[0] * v[0][i].z + wa[1] * v[1][i].z;
        p.w = wa[0] * v[0][i].w + wa[1] * v[1][i].w;
        pw[i * 32 + lane] = p;
    }
    __syncthreads();

    // ---- 7. reduce 16 partials, RED.ADD into out (out pre-set to x) ----
    float acc = 0.0f;
#pragma unroll
    for (int wq = 0; wq < NWARP; wq++)
        acc += s_part[wq * D_DIM + tid];

    atomicAdd(&out[(size_t)b * D_DIM + tid], acc);   // result unused -> REDG
}

extern "C" void kernel_launch(void* const* d_in, const int* in_sizes, int n_in,
                              void* d_out, int out_size) {
    const float* x       = (const float*)d_in[0];
    const int*   indices = (const int*)d_in[1];
    const float* weights = (const float*)d_in[2];
    const float* pool    = (const float*)d_in[3];
    float*       out     = (float*)d_out;

    cudaFuncSetAttribute(sparse_gather_kernel,
                         cudaFuncAttributeMaxDynamicSharedMemorySize, SMEM_BYTES);

    init_kernel<<<(B_DIM * D_DIM / 4) / INIT_THREADS, INIT_THREADS>>>(x, out);

    sparse_gather_kernel<<<B_DIM * SPLIT, THREADS, SMEM_BYTES>>>(
        x, indices, weights, pool, out);
}